// round 2
// baseline (speedup 1.0000x reference)
#include <cuda_runtime.h>
#include <cuda_bf16.h>
#include <cstdint>

// LearnedTaskSpecificLinear: out[n,o] = sum_i x[n,i] * W[task_ids[n], i, o]
// N_ROWS=2048, IN=OUT=512, NUM_TASKS=64.
//
// Block = (task, 128-col tile). Block scans task_ids, builds its row list in
// shared memory, then tiled fp32 GEMM M=32 x N=128 x K=32 with packed
// fma.rn.f32x2 so each W[t] panel is read from HBM once per col-tile.
//
// task_ids dtype is detected at runtime (int32 vs int64): viewing the buffer
// as int32 words, int64 data (values 0..63, little-endian) has all odd-index
// words == 0; int32 data has task ids there (nonzero w.p. 63/64 each).

#define NUM_TASKS 64
#define N_ROWS    2048
#define IN_SIZE   512
#define OUT_SIZE  512

#define M_TILE 32
#define N_TILE 128
#define K_TILE 32
#define NTHREADS 256

typedef unsigned long long ull;

__device__ __forceinline__ ull fma2(ull a, ull b, ull c) {
    ull d;
    asm("fma.rn.f32x2 %0, %1, %2, %3;" : "=l"(d) : "l"(a), "l"(b), "l"(c));
    return d;
}
__device__ __forceinline__ ull pack2(float lo, float hi) {
    ull d;
    asm("mov.b64 %0, {%1, %2};" : "=l"(d) : "f"(lo), "f"(hi));
    return d;
}
__device__ __forceinline__ void unpack2(ull v, float& lo, float& hi) {
    asm("mov.b64 {%0, %1}, %2;" : "=f"(lo), "=f"(hi) : "l"(v));
}

__global__ __launch_bounds__(NTHREADS, 2)
void task_linear_kernel(const float* __restrict__ x,
                        const int* __restrict__ tid32,
                        const float* __restrict__ W,
                        float* __restrict__ out) {
    const int t  = blockIdx.x;   // task
    const int ct = blockIdx.y;   // column tile (N_TILE cols)
    const int tid = threadIdx.x;
    const int tx = tid & 31;     // 32 col-groups of 4 cols
    const int ty = tid >> 5;     // 8 row-groups of 4 rows

    __shared__ int rows[N_ROWS];
    __shared__ int s_cnt;
    __shared__ int s_is64;
    __shared__ __align__(16) float xs[K_TILE][M_TILE + 2];
    __shared__ __align__(16) float ws[K_TILE][N_TILE];

    if (tid == 0) { s_cnt = 0; s_is64 = 0; }
    __syncthreads();

    // dtype detection: OR together odd-index 32-bit words of the first 256
    // logical entries. Zero => int64 (stride 2), nonzero => int32 (stride 1).
    {
        int v = 0;
        for (int i = tid; i < 256; i += NTHREADS) v |= tid32[2 * i + 1];
        #pragma unroll
        for (int o = 16; o > 0; o >>= 1) v |= __shfl_xor_sync(0xffffffffu, v, o);
        if ((tid & 31) == 0 && v == 0) s_is64 = 1;   // benign race, same value
    }
    __syncthreads();
    const int stride = s_is64 ? 2 : 1;

    // Self-select rows for this task (order nondeterministic; output isn't).
    for (int i = tid; i < N_ROWS; i += NTHREADS) {
        if (tid32[i * stride] == t) {
            int p = atomicAdd(&s_cnt, 1);
            rows[p] = i;
        }
    }
    __syncthreads();
    const int n = s_cnt;

    const float* Wbase = W + ((size_t)t * IN_SIZE) * OUT_SIZE + (size_t)ct * N_TILE;

    for (int m0 = 0; m0 < n; m0 += M_TILE) {
        const int mrem = n - m0;

        ull acc[2][4];
        #pragma unroll
        for (int rp = 0; rp < 2; rp++)
            #pragma unroll
            for (int c = 0; c < 4; c++) acc[rp][c] = 0ULL;

        for (int k0 = 0; k0 < IN_SIZE; k0 += K_TILE) {
            __syncthreads();  // previous tile fully consumed

            // x tile: M_TILE rows x K_TILE cols (zero-pad partial chunk)
            #pragma unroll
            for (int j = tid; j < M_TILE * K_TILE; j += NTHREADS) {
                int r  = j >> 5;
                int kk = j & 31;
                float v = 0.0f;
                if (r < mrem)
                    v = x[(size_t)rows[m0 + r] * IN_SIZE + k0 + kk];
                xs[kk][r] = v;
            }

            // W tile: K_TILE rows x N_TILE cols (float4, coalesced)
            #pragma unroll
            for (int j = tid; j < K_TILE * (N_TILE / 4); j += NTHREADS) {
                int kk = j >> 5;
                int c4 = j & 31;
                *(float4*)&ws[kk][c4 * 4] =
                    *(const float4*)&Wbase[(size_t)(k0 + kk) * OUT_SIZE + c4 * 4];
            }
            __syncthreads();

            #pragma unroll 8
            for (int kk = 0; kk < K_TILE; kk++) {
                ull a01 = *(const ull*)&xs[kk][ty * 4];
                ull a23 = *(const ull*)&xs[kk][ty * 4 + 2];
                float4 b = *(const float4*)&ws[kk][tx * 4];
                ull b0 = pack2(b.x, b.x);
                ull b1 = pack2(b.y, b.y);
                ull b2 = pack2(b.z, b.z);
                ull b3 = pack2(b.w, b.w);
                acc[0][0] = fma2(a01, b0, acc[0][0]);
                acc[0][1] = fma2(a01, b1, acc[0][1]);
                acc[0][2] = fma2(a01, b2, acc[0][2]);
                acc[0][3] = fma2(a01, b3, acc[0][3]);
                acc[1][0] = fma2(a23, b0, acc[1][0]);
                acc[1][1] = fma2(a23, b1, acc[1][1]);
                acc[1][2] = fma2(a23, b2, acc[1][2]);
                acc[1][3] = fma2(a23, b3, acc[1][3]);
            }
        }

        #pragma unroll
        for (int rp = 0; rp < 2; rp++) {
            float lo0, hi0, lo1, hi1, lo2, hi2, lo3, hi3;
            unpack2(acc[rp][0], lo0, hi0);
            unpack2(acc[rp][1], lo1, hi1);
            unpack2(acc[rp][2], lo2, hi2);
            unpack2(acc[rp][3], lo3, hi3);
            int r0 = m0 + ty * 4 + rp * 2;
            if (r0 < n) {
                float4 v = make_float4(lo0, lo1, lo2, lo3);
                *(float4*)&out[(size_t)rows[r0] * OUT_SIZE + ct * N_TILE + tx * 4] = v;
            }
            int r1 = r0 + 1;
            if (r1 < n) {
                float4 v = make_float4(hi0, hi1, hi2, hi3);
                *(float4*)&out[(size_t)rows[r1] * OUT_SIZE + ct * N_TILE + tx * 4] = v;
            }
        }
    }
}

extern "C" void kernel_launch(void* const* d_in, const int* in_sizes, int n_in,
                              void* d_out, int out_size) {
    // Assign inputs by element count, not position.
    const float* x = nullptr;
    const int*   tids = nullptr;
    const float* W = nullptr;
    for (int i = 0; i < n_in; i++) {
        if (in_sizes[i] == N_ROWS * IN_SIZE)             x = (const float*)d_in[i];
        else if (in_sizes[i] == N_ROWS)                  tids = (const int*)d_in[i];
        else if (in_sizes[i] == NUM_TASKS * IN_SIZE * OUT_SIZE) W = (const float*)d_in[i];
    }
    float* out = (float*)d_out;

    dim3 grid(NUM_TASKS, OUT_SIZE / N_TILE);  // 64 x 4
    task_linear_kernel<<<grid, NTHREADS>>>(x, tids, W, out);
}

// round 6
// speedup vs baseline: 1.3962x; 1.3962x over previous
#include <cuda_runtime.h>
#include <cuda_bf16.h>
#include <cstdint>

// LearnedTaskSpecificLinear: out[n,o] = sum_i x[n,i] * W[task_ids[n], i, o]
// N_ROWS=2048, IN=OUT=512, NUM_TASKS=64.
//
// Block = (task, 128-col tile, m-slot). Row list built DETERMINISTICALLY
// (index order, prefix-scan) so slot blocks partition by list position safely.
// GEMM M=32 x N=128 x K=512, K_TILE=32, synchronous register-prefetch double
// buffering, packed fma.rn.f32x2.

#define NUM_TASKS 64
#define N_ROWS    2048
#define IN_SIZE   512
#define OUT_SIZE  512

#define M_TILE 32
#define N_TILE 128
#define K_TILE 32
#define NTHREADS 256
#define N_KTILES (IN_SIZE / K_TILE)   // 16
#define M_SLOTS 2
#define PER_THREAD (N_ROWS / NTHREADS) // 8

typedef unsigned long long ull;

__device__ __forceinline__ ull fma2(ull a, ull b, ull c) {
    ull d;
    asm("fma.rn.f32x2 %0, %1, %2, %3;" : "=l"(d) : "l"(a), "l"(b), "l"(c));
    return d;
}
__device__ __forceinline__ ull pack2(float lo, float hi) {
    ull d;
    asm("mov.b64 %0, {%1, %2};" : "=l"(d) : "f"(lo), "f"(hi));
    return d;
}
__device__ __forceinline__ void unpack2(ull v, float& lo, float& hi) {
    asm("mov.b64 {%0, %1}, %2;" : "=f"(lo), "=f"(hi) : "l"(v));
}

__global__ __launch_bounds__(NTHREADS, 2)
void task_linear_kernel(const float* __restrict__ x,
                        const int* __restrict__ tid32,
                        const float* __restrict__ W,
                        float* __restrict__ out) {
    const int t    = blockIdx.x;
    const int ct   = blockIdx.y;
    const int slot = blockIdx.z;
    const int tid  = threadIdx.x;
    const int tx = tid & 31;     // 32 col-groups of 4 cols
    const int ty = tid >> 5;     // 8 row-groups of 4 rows
    const int lane = tid & 31;
    const int wrp  = tid >> 5;

    __shared__ unsigned short rows[N_ROWS];
    __shared__ int s_is64;
    __shared__ int warp_sums[NTHREADS / 32];
    __shared__ int s_n;
    __shared__ __align__(16) float xs[2][K_TILE][M_TILE + 2];
    __shared__ __align__(16) float ws[2][K_TILE][N_TILE];

    if (tid == 0) s_is64 = 0;
    __syncthreads();

    // dtype detection (int32 vs int64 task_ids): odd-index 32-bit words of
    // int64 data (values 0..63, LE) are all zero.
    {
        int v = 0;
        for (int i = tid; i < 256; i += NTHREADS) v |= tid32[2 * i + 1];
        #pragma unroll
        for (int o = 16; o > 0; o >>= 1) v |= __shfl_xor_sync(0xffffffffu, v, o);
        if (lane == 0 && v == 0) s_is64 = 1;  // benign same-value race
    }
    __syncthreads();
    const int stride = s_is64 ? 2 : 1;

    // ---- Deterministic row list (index order) via prefix scan ----
    // Thread tid owns indices [tid*8, tid*8+8).
    {
        const int base = tid * PER_THREAD;
        int match = 0;                    // bitmask of matches
        #pragma unroll
        for (int j = 0; j < PER_THREAD; j++)
            if (tid32[(base + j) * stride] == t) match |= (1 << j);
        int c = __popc(match);

        // warp-inclusive scan of c
        int incl = c;
        #pragma unroll
        for (int o = 1; o < 32; o <<= 1) {
            int v = __shfl_up_sync(0xffffffffu, incl, o);
            if (lane >= o) incl += v;
        }
        if (lane == 31) warp_sums[wrp] = incl;
        __syncthreads();

        int warp_off = 0;
        #pragma unroll
        for (int w = 0; w < NTHREADS / 32; w++)
            if (w < wrp) warp_off += warp_sums[w];
        int pos = warp_off + incl - c;    // exclusive position

        #pragma unroll
        for (int j = 0; j < PER_THREAD; j++)
            if (match & (1 << j)) rows[pos++] = (unsigned short)(base + j);

        if (tid == NTHREADS - 1) s_n = pos;  // total count
    }
    __syncthreads();
    const int n = s_n;

    const float* Wbase = W + ((size_t)t * IN_SIZE) * OUT_SIZE + (size_t)ct * N_TILE;

    // Per-thread load assignments (constant across tiles):
    const int xr = tid >> 3;   // 0..31 (x row within tile)
    const int xc = tid & 7;    // 0..7  (float4 chunk along k)

    for (int m0 = slot * M_TILE; m0 < n; m0 += M_SLOTS * M_TILE) {
        ull acc[2][4];
        #pragma unroll
        for (int rp = 0; rp < 2; rp++)
            #pragma unroll
            for (int c = 0; c < 4; c++) acc[rp][c] = 0ULL;

        const bool xp = (m0 + xr) < n;
        const size_t xrow = (size_t)(xp ? rows[m0 + xr] : 0) * IN_SIZE;

        float4 xreg;
        float4 wreg[4];

        auto load_tile = [&](int kt) {
            const int k0 = kt * K_TILE;
            xreg = xp ? *(const float4*)&x[xrow + k0 + xc * 4]
                      : make_float4(0.f, 0.f, 0.f, 0.f);
            #pragma unroll
            for (int q = 0; q < 4; q++) {
                int j  = tid + q * NTHREADS;
                int kk = j >> 5;
                int c4 = j & 31;
                wreg[q] = *(const float4*)&Wbase[(size_t)(k0 + kk) * OUT_SIZE + c4 * 4];
            }
        };
        auto store_tile = [&](int buf) {
            xs[buf][xc * 4 + 0][xr] = xreg.x;
            xs[buf][xc * 4 + 1][xr] = xreg.y;
            xs[buf][xc * 4 + 2][xr] = xreg.z;
            xs[buf][xc * 4 + 3][xr] = xreg.w;
            #pragma unroll
            for (int q = 0; q < 4; q++) {
                int j  = tid + q * NTHREADS;
                int kk = j >> 5;
                int c4 = j & 31;
                *(float4*)&ws[buf][kk][c4 * 4] = wreg[q];
            }
        };

        load_tile(0);
        store_tile(0);
        __syncthreads();

        for (int kt = 0; kt < N_KTILES; kt++) {
            const int buf = kt & 1;
            if (kt + 1 < N_KTILES) load_tile(kt + 1);  // LDGs fly over compute

            #pragma unroll 8
            for (int kk = 0; kk < K_TILE; kk++) {
                ull a01 = *(const ull*)&xs[buf][kk][ty * 4];      // broadcast
                ull a23 = *(const ull*)&xs[buf][kk][ty * 4 + 2];
                float4 b4 = *(const float4*)&ws[buf][kk][tx * 4]; // conflict-free
                ull b0 = pack2(b4.x, b4.x);
                ull b1 = pack2(b4.y, b4.y);
                ull b2 = pack2(b4.z, b4.z);
                ull b3 = pack2(b4.w, b4.w);
                acc[0][0] = fma2(a01, b0, acc[0][0]);
                acc[0][1] = fma2(a01, b1, acc[0][1]);
                acc[0][2] = fma2(a01, b2, acc[0][2]);
                acc[0][3] = fma2(a01, b3, acc[0][3]);
                acc[1][0] = fma2(a23, b0, acc[1][0]);
                acc[1][1] = fma2(a23, b1, acc[1][1]);
                acc[1][2] = fma2(a23, b2, acc[1][2]);
                acc[1][3] = fma2(a23, b3, acc[1][3]);
            }
            __syncthreads();                 // all reads of prev buf done
            if (kt + 1 < N_KTILES) store_tile(buf ^ 1);
            __syncthreads();                 // writes visible before next read
        }

        // epilogue: 4 rows x 4 cols per thread
        #pragma unroll
        for (int rp = 0; rp < 2; rp++) {
            float lo0, hi0, lo1, hi1, lo2, hi2, lo3, hi3;
            unpack2(acc[rp][0], lo0, hi0);
            unpack2(acc[rp][1], lo1, hi1);
            unpack2(acc[rp][2], lo2, hi2);
            unpack2(acc[rp][3], lo3, hi3);
            int r0 = m0 + ty * 4 + rp * 2;
            if (r0 < n) {
                float4 v = make_float4(lo0, lo1, lo2, lo3);
                *(float4*)&out[(size_t)rows[r0] * OUT_SIZE + ct * N_TILE + tx * 4] = v;
            }
            int r1 = r0 + 1;
            if (r1 < n) {
                float4 v = make_float4(hi0, hi1, hi2, hi3);
                *(float4*)&out[(size_t)rows[r1] * OUT_SIZE + ct * N_TILE + tx * 4] = v;
            }
        }
    }
}

extern "C" void kernel_launch(void* const* d_in, const int* in_sizes, int n_in,
                              void* d_out, int out_size) {
    const float* x = nullptr;
    const int*   tids = nullptr;
    const float* W = nullptr;
    for (int i = 0; i < n_in; i++) {
        if (in_sizes[i] == N_ROWS * IN_SIZE)                    x = (const float*)d_in[i];
        else if (in_sizes[i] == N_ROWS)                         tids = (const int*)d_in[i];
        else if (in_sizes[i] == NUM_TASKS * IN_SIZE * OUT_SIZE) W = (const float*)d_in[i];
    }
    float* out = (float*)d_out;

    dim3 grid(NUM_TASKS, OUT_SIZE / N_TILE, M_SLOTS);  // 64 x 4 x 2
    task_linear_kernel<<<grid, NTHREADS>>>(x, tids, W, out);
}